// round 3
// baseline (speedup 1.0000x reference)
#include <cuda_runtime.h>
#include <math.h>

// learned mask M (8x8) and DCT basis C (8x8), produced by prep_kernel
static __device__ float g_C[64];
static __device__ float g_M[64];

__global__ void prep_kernel(const float* __restrict__ noise,
                            const float* __restrict__ qmat,
                            const float* __restrict__ qmw,
                            const float* __restrict__ w1, const float* __restrict__ b1,
                            const float* __restrict__ w2, const float* __restrict__ b2,
                            const float* __restrict__ w3, const float* __restrict__ b3)
{
    __shared__ float h1[16], h2[16], nr[18], coef[16];
    int t = threadIdx.x;  // 64 threads

    // DCT matrix. float cos is ~1e-7 accurate vs the double reference; tol is 1e-3.
    if (t < 64) {
        int i = t >> 3, j = t & 7;
        const float PI = 3.1415926f;
        float v;
        if (i == 0) v = sqrtf(1.0f / 8.0f);
        else        v = cosf(PI * (float)i * (float)(2 * j + 1) / 16.0f) * sqrtf(2.0f / 8.0f);
        g_C[t] = v;
    }

    const float inv_sqrt2 = 0.7071067811865476f;
    // layer 1: 16 lanes in parallel
    if (t < 16) {
        float z = fmaf(noise[0], w1[t], b1[t]);
        h1[t] = 0.5f * z * (1.0f + erff(z * inv_sqrt2));
    }
    __syncthreads();
    if (t < 16) {
        float z = b2[t];
        #pragma unroll
        for (int k = 0; k < 16; k++) z = fmaf(h1[k], w2[k * 16 + t], z);
        h2[t] = 0.5f * z * (1.0f + erff(z * inv_sqrt2));
    }
    __syncthreads();
    if (t < 18) {
        float z = b3[t];
        #pragma unroll
        for (int k = 0; k < 16; k++) z = fmaf(h2[k], w3[k * 18 + t], z);
        nr[t] = z;
    }
    __syncthreads();
    if (t == 0) {
        float mx = qmw[0];
        #pragma unroll
        for (int i = 1; i < 16; i++) mx = fmaxf(mx, qmw[i]);
        float e[16], sum = 0.f;
        #pragma unroll
        for (int i = 0; i < 16; i++) { e[i] = expf(qmw[i] - mx); sum += e[i]; }
        float inv = 1.0f / sum;
        #pragma unroll
        for (int i = 0; i < 16; i++)
            coef[i] = (e[i] * inv * nr[0] + nr[1]) * nr[2 + i];
    }
    __syncthreads();

    if (t < 64) {
        float s = 0.f;
        #pragma unroll
        for (int i = 0; i < 16; i++) s = fmaf(coef[i], qmat[i * 64 + t], s);
        g_M[t] = s;
    }
}

// One thread per 8x8 block, register-lean streaming formulation:
//   V = C * (X * C^T)   built by streaming X rows (X not kept)
//   V = V .* M
//   per output row i: T = (C^T V)_i ; low_i = T*C ; high_i = (reload X row i) - low_i
__global__ __launch_bounds__(128, 5) void dct_main(const float* __restrict__ x,
                                                   float* __restrict__ lo,
                                                   float* __restrict__ hi)
{
    __shared__ float Cs[64];
    __shared__ float Ms[64];
    int tid = threadIdx.x;
    if (tid < 64) { Cs[tid] = g_C[tid]; Ms[tid] = g_M[tid]; }
    __syncthreads();

    int g   = blockIdx.x * 128 + tid;        // global 8x8-block id, < 524288
    int img = g >> 6;                        // image id (B*Ch)
    int blk = g & 63;                        // block within 64x64 image
    int off = (img << 12) + ((blk >> 3) << 9) + ((blk & 7) << 3);

    const float* xp = x + off;
    float* lp = lo + off;
    float* hp = hi + off;

    // Phase 1: V = C * (X * C^T), streaming X one row at a time.
    float V[64];
    #pragma unroll
    for (int k = 0; k < 64; k++) V[k] = 0.0f;

    #pragma unroll
    for (int j = 0; j < 8; j++) {
        float4 a = *reinterpret_cast<const float4*>(xp + (j << 6));
        float4 b = *reinterpret_cast<const float4*>(xp + (j << 6) + 4);
        float r[8] = {a.x, a.y, a.z, a.w, b.x, b.y, b.z, b.w};

        // U = Xrow_j * C^T : U[m] = sum_k r[k] * C[m][k]
        float U[8];
        #pragma unroll
        for (int m = 0; m < 8; m++) {
            float s = r[0] * Cs[m * 8 + 0];
            #pragma unroll
            for (int k = 1; k < 8; k++) s = fmaf(r[k], Cs[m * 8 + k], s);
            U[m] = s;
        }
        // V[i][m] += C[i][j] * U[m]
        #pragma unroll
        for (int i = 0; i < 8; i++) {
            float c = Cs[i * 8 + j];
            #pragma unroll
            for (int m = 0; m < 8; m++) V[i * 8 + m] = fmaf(c, U[m], V[i * 8 + m]);
        }
    }

    // mask
    #pragma unroll
    for (int k = 0; k < 64; k++) V[k] *= Ms[k];

    // Phase 2: per output row i
    #pragma unroll
    for (int i = 0; i < 8; i++) {
        // reload X row i early (L1 hit) to overlap with FMAs below
        float4 a = *reinterpret_cast<const float4*>(xp + (i << 6));
        float4 b = *reinterpret_cast<const float4*>(xp + (i << 6) + 4);

        // T[k] = sum_j C[j][i] * V[j][k]
        float T[8];
        #pragma unroll
        for (int k = 0; k < 8; k++) {
            float s = Cs[i] * V[k];
            #pragma unroll
            for (int j = 1; j < 8; j++) s = fmaf(Cs[j * 8 + i], V[j * 8 + k], s);
            T[k] = s;
        }
        // low[m] = sum_k T[k] * C[k][m]
        float l[8];
        #pragma unroll
        for (int m = 0; m < 8; m++) {
            float s = T[0] * Cs[m];
            #pragma unroll
            for (int k = 1; k < 8; k++) s = fmaf(T[k], Cs[k * 8 + m], s);
            l[m] = s;
        }
        *reinterpret_cast<float4*>(lp + (i << 6))     = make_float4(l[0], l[1], l[2], l[3]);
        *reinterpret_cast<float4*>(lp + (i << 6) + 4) = make_float4(l[4], l[5], l[6], l[7]);
        *reinterpret_cast<float4*>(hp + (i << 6)) =
            make_float4(a.x - l[0], a.y - l[1], a.z - l[2], a.w - l[3]);
        *reinterpret_cast<float4*>(hp + (i << 6) + 4) =
            make_float4(b.x - l[4], b.y - l[5], b.z - l[6], b.w - l[7]);
    }
}

extern "C" void kernel_launch(void* const* d_in, const int* in_sizes, int n_in,
                              void* d_out, int out_size)
{
    const float* x     = (const float*)d_in[0];
    const float* noise = (const float*)d_in[1];
    const float* qmat  = (const float*)d_in[2];
    const float* qmw   = (const float*)d_in[3];
    const float* w1    = (const float*)d_in[4];
    const float* b1    = (const float*)d_in[5];
    const float* w2    = (const float*)d_in[6];
    const float* b2    = (const float*)d_in[7];
    const float* w3    = (const float*)d_in[8];
    const float* b3    = (const float*)d_in[9];

    float* out = (float*)d_out;
    int N = out_size / 2;                 // elements per output tensor
    float* lo = out;
    float* hi = out + N;

    prep_kernel<<<1, 64>>>(noise, qmat, qmw, w1, b1, w2, b2, w3, b3);

    int nblocks8x8 = N / 64;              // one thread per 8x8 block
    dct_main<<<nblocks8x8 / 128, 128>>>(x, lo, hi);
}

// round 4
// speedup vs baseline: 1.1774x; 1.1774x over previous
#include <cuda_runtime.h>
#include <math.h>

// learned mask M (8x8) and DCT basis C (8x8), produced by prep_kernel
static __device__ float g_C[64];
static __device__ float g_M[64];

__global__ void prep_kernel(const float* __restrict__ noise,
                            const float* __restrict__ qmat,
                            const float* __restrict__ qmw,
                            const float* __restrict__ w1, const float* __restrict__ b1,
                            const float* __restrict__ w2, const float* __restrict__ b2,
                            const float* __restrict__ w3, const float* __restrict__ b3)
{
    __shared__ float h1[16], h2[16], nr[18], coef[16];
    int t = threadIdx.x;  // 64 threads

    if (t < 64) {
        int i = t >> 3, j = t & 7;
        const float PI = 3.1415926f;
        float v;
        if (i == 0) v = sqrtf(1.0f / 8.0f);
        else        v = cosf(PI * (float)i * (float)(2 * j + 1) / 16.0f) * sqrtf(2.0f / 8.0f);
        g_C[t] = v;
    }

    const float inv_sqrt2 = 0.7071067811865476f;
    if (t < 16) {
        float z = fmaf(noise[0], w1[t], b1[t]);
        h1[t] = 0.5f * z * (1.0f + erff(z * inv_sqrt2));
    }
    __syncthreads();
    if (t < 16) {
        float z = b2[t];
        #pragma unroll
        for (int k = 0; k < 16; k++) z = fmaf(h1[k], w2[k * 16 + t], z);
        h2[t] = 0.5f * z * (1.0f + erff(z * inv_sqrt2));
    }
    __syncthreads();
    if (t < 18) {
        float z = b3[t];
        #pragma unroll
        for (int k = 0; k < 16; k++) z = fmaf(h2[k], w3[k * 18 + t], z);
        nr[t] = z;
    }
    __syncthreads();
    if (t == 0) {
        float mx = qmw[0];
        #pragma unroll
        for (int i = 1; i < 16; i++) mx = fmaxf(mx, qmw[i]);
        float e[16], sum = 0.f;
        #pragma unroll
        for (int i = 0; i < 16; i++) { e[i] = expf(qmw[i] - mx); sum += e[i]; }
        float inv = 1.0f / sum;
        #pragma unroll
        for (int i = 0; i < 16; i++)
            coef[i] = (e[i] * inv * nr[0] + nr[1]) * nr[2 + i];
    }
    __syncthreads();

    if (t < 64) {
        float s = 0.f;
        #pragma unroll
        for (int i = 0; i < 16; i++) s = fmaf(coef[i], qmat[i * 64 + t], s);
        g_M[t] = s;
    }
}

// xor-transpose of an 8x8 tile held row-per-lane across 8 lanes (3 rounds, 12 SHFL)
__device__ __forceinline__ void transpose8(float a[8], int lane)
{
    #pragma unroll
    for (int dd = 0; dd < 3; dd++) {
        const int d = 4 >> dd;
        #pragma unroll
        for (int k = 0; k < 8; k++) {
            if ((k & d) == 0) {
                bool up = (lane & d) != 0;
                float send = up ? a[k] : a[k + d];
                float got  = __shfl_xor_sync(0xffffffffu, send, d);
                if (up) a[k] = got; else a[k + d] = got;
            }
        }
    }
}

// 8 lanes cooperate on one 8x8 block; lane r owns row r.
// low = C^T((C X C^T).*M)C ; high = X - low. x read exactly once.
__global__ __launch_bounds__(128) void dct_main(const float* __restrict__ x,
                                                float* __restrict__ lo,
                                                float* __restrict__ hi)
{
    __shared__ float Cs[64];
    __shared__ float Ms[64];
    int tid = threadIdx.x;
    if (tid < 64) { Cs[tid] = g_C[tid]; Ms[tid] = g_M[tid]; }
    __syncthreads();

    int lane = tid & 7;                       // row within block
    int g    = blockIdx.x * 16 + (tid >> 3);  // global 8x8-block id
    int img  = g >> 6;
    int blk  = g & 63;
    int off  = (img << 12) + ((blk >> 3) << 9) + ((blk & 7) << 3) + (lane << 6);

    const float* xp = x + off;
    float4 a0 = *reinterpret_cast<const float4*>(xp);
    float4 a1 = *reinterpret_cast<const float4*>(xp + 4);
    float X[8] = {a0.x, a0.y, a0.z, a0.w, a1.x, a1.y, a1.z, a1.w};

    // A = Xrow * C^T : A[m] = sum_k X[k] * C[m][k]
    float A[8];
    #pragma unroll
    for (int m = 0; m < 8; m++) {
        float s = X[0] * Cs[m * 8];
        #pragma unroll
        for (int k = 1; k < 8; k++) s = fmaf(X[k], Cs[m * 8 + k], s);
        A[m] = s;
    }

    transpose8(A, lane);   // lane r now holds column r of A

    // Y col r = C * A_col ; then mask with column r of M
    float Y[8];
    #pragma unroll
    for (int i = 0; i < 8; i++) {
        float s = Cs[i * 8] * A[0];
        #pragma unroll
        for (int j = 1; j < 8; j++) s = fmaf(Cs[i * 8 + j], A[j], s);
        Y[i] = s * Ms[i * 8 + lane];
    }

    // Z col r = C^T * Y_col : Z[i] = sum_j C[j][i] * Y[j]
    float Z[8];
    #pragma unroll
    for (int i = 0; i < 8; i++) {
        float s = Cs[i] * Y[0];
        #pragma unroll
        for (int j = 1; j < 8; j++) s = fmaf(Cs[j * 8 + i], Y[j], s);
        Z[i] = s;
    }

    transpose8(Z, lane);   // lane r now holds row r of Z

    // low row = Zrow * C : l[m] = sum_k Z[k] * C[k][m]
    float l[8];
    #pragma unroll
    for (int m = 0; m < 8; m++) {
        float s = Z[0] * Cs[m];
        #pragma unroll
        for (int k = 1; k < 8; k++) s = fmaf(Z[k], Cs[k * 8 + m], s);
        l[m] = s;
    }

    float* lp = lo + off;
    float* hp = hi + off;
    *reinterpret_cast<float4*>(lp)     = make_float4(l[0], l[1], l[2], l[3]);
    *reinterpret_cast<float4*>(lp + 4) = make_float4(l[4], l[5], l[6], l[7]);
    *reinterpret_cast<float4*>(hp) =
        make_float4(X[0] - l[0], X[1] - l[1], X[2] - l[2], X[3] - l[3]);
    *reinterpret_cast<float4*>(hp + 4) =
        make_float4(X[4] - l[4], X[5] - l[5], X[6] - l[6], X[7] - l[7]);
}

extern "C" void kernel_launch(void* const* d_in, const int* in_sizes, int n_in,
                              void* d_out, int out_size)
{
    const float* x     = (const float*)d_in[0];
    const float* noise = (const float*)d_in[1];
    const float* qmat  = (const float*)d_in[2];
    const float* qmw   = (const float*)d_in[3];
    const float* w1    = (const float*)d_in[4];
    const float* b1    = (const float*)d_in[5];
    const float* w2    = (const float*)d_in[6];
    const float* b2    = (const float*)d_in[7];
    const float* w3    = (const float*)d_in[8];
    const float* b3    = (const float*)d_in[9];

    float* out = (float*)d_out;
    int N = out_size / 2;                 // elements per output tensor
    float* lo = out;
    float* hi = out + N;

    prep_kernel<<<1, 64>>>(noise, qmat, qmw, w1, b1, w2, b2, w3, b3);

    int nblocks8x8 = N / 64;              // 8 lanes per block, 16 blocks per CTA
    dct_main<<<nblocks8x8 / 16, 128>>>(x, lo, hi);
}

// round 5
// speedup vs baseline: 1.3616x; 1.1564x over previous
#include <cuda_runtime.h>
#include <math.h>

// ---- DCT basis as compile-time immediates -------------------------------
// 0.5*cos(k*pi/16) family + sqrt(1/8). Matches the reference's truncated-pi
// basis to <4e-7 (tolerance is 1e-3).
#define P0 0.35355339059327373f
#define P1 0.4903926402016152f
#define P2 0.46193976625564337f
#define P3 0.4157348061512726f
#define P4 0.3535533905932738f
#define P5 0.2777851165098011f
#define P6 0.1913417161825449f
#define P7 0.09754516100806412f

#define DOT8(v,c0,c1,c2,c3,c4,c5,c6,c7) \
    fmaf((v)[7],(c7),fmaf((v)[6],(c6),fmaf((v)[5],(c5),fmaf((v)[4],(c4), \
    fmaf((v)[3],(c3),fmaf((v)[2],(c2),fmaf((v)[1],(c1),(v)[0]*(c0))))))))

// dst = C * src   (dst[i] = row_i(C) . src)
#define MUL_ROWS(dst, src) do { \
    (dst)[0] = DOT8(src, P0, P0, P0, P0, P0, P0, P0, P0); \
    (dst)[1] = DOT8(src, P1, P3, P5, P7,-P7,-P5,-P3,-P1); \
    (dst)[2] = DOT8(src, P2, P6,-P6,-P2,-P2,-P6, P6, P2); \
    (dst)[3] = DOT8(src, P3,-P7,-P1,-P5, P5, P1, P7,-P3); \
    (dst)[4] = DOT8(src, P4,-P4,-P4, P4, P4,-P4,-P4, P4); \
    (dst)[5] = DOT8(src, P5,-P1, P7, P3,-P3,-P7, P1,-P5); \
    (dst)[6] = DOT8(src, P6,-P2, P2,-P6,-P6, P2,-P2, P6); \
    (dst)[7] = DOT8(src, P7,-P5, P3,-P1, P1,-P3, P5,-P7); \
} while (0)

// dst = C^T * src (dst[i] = col_i(C) . src)
#define MUL_COLS(dst, src) do { \
    (dst)[0] = DOT8(src, P0, P1, P2, P3, P4, P5, P6, P7); \
    (dst)[1] = DOT8(src, P0, P3, P6,-P7,-P4,-P1,-P2,-P5); \
    (dst)[2] = DOT8(src, P0, P5,-P6,-P1,-P4, P7, P2, P3); \
    (dst)[3] = DOT8(src, P0, P7,-P2,-P5, P4, P3,-P6,-P1); \
    (dst)[4] = DOT8(src, P0,-P7,-P2, P5, P4,-P3,-P6, P1); \
    (dst)[5] = DOT8(src, P0,-P5,-P6, P1,-P4,-P7, P2,-P3); \
    (dst)[6] = DOT8(src, P0,-P3, P6, P7,-P4, P1,-P2, P5); \
    (dst)[7] = DOT8(src, P0,-P1, P2,-P3, P4,-P5, P6,-P7); \
} while (0)

// learned mask M (8x8), produced by prep_kernel
static __device__ float g_M[64];

__global__ void prep_kernel(const float* __restrict__ noise,
                            const float* __restrict__ qmat,
                            const float* __restrict__ qmw,
                            const float* __restrict__ w1, const float* __restrict__ b1,
                            const float* __restrict__ w2, const float* __restrict__ b2,
                            const float* __restrict__ w3, const float* __restrict__ b3)
{
    __shared__ float h1[16], h2[16], nr[18], coef[16];
    int t = threadIdx.x;  // 64 threads

    const float inv_sqrt2 = 0.7071067811865476f;
    if (t < 16) {
        float z = fmaf(noise[0], w1[t], b1[t]);
        h1[t] = 0.5f * z * (1.0f + erff(z * inv_sqrt2));
    }
    __syncthreads();
    if (t < 16) {
        float z = b2[t];
        #pragma unroll
        for (int k = 0; k < 16; k++) z = fmaf(h1[k], w2[k * 16 + t], z);
        h2[t] = 0.5f * z * (1.0f + erff(z * inv_sqrt2));
    }
    __syncthreads();
    if (t < 18) {
        float z = b3[t];
        #pragma unroll
        for (int k = 0; k < 16; k++) z = fmaf(h2[k], w3[k * 18 + t], z);
        nr[t] = z;
    }
    __syncthreads();
    if (t == 0) {
        float mx = qmw[0];
        #pragma unroll
        for (int i = 1; i < 16; i++) mx = fmaxf(mx, qmw[i]);
        float e[16], sum = 0.f;
        #pragma unroll
        for (int i = 0; i < 16; i++) { e[i] = expf(qmw[i] - mx); sum += e[i]; }
        float inv = 1.0f / sum;
        #pragma unroll
        for (int i = 0; i < 16; i++)
            coef[i] = (e[i] * inv * nr[0] + nr[1]) * nr[2 + i];
    }
    __syncthreads();

    if (t < 64) {
        float s = 0.f;
        #pragma unroll
        for (int i = 0; i < 16; i++) s = fmaf(coef[i], qmat[i * 64 + t], s);
        g_M[t] = s;
    }
}

// xor-transpose of an 8x8 tile held row-per-lane across 8 lanes (12 SHFL)
__device__ __forceinline__ void transpose8(float a[8], int lane)
{
    #pragma unroll
    for (int dd = 0; dd < 3; dd++) {
        const int d = 4 >> dd;
        #pragma unroll
        for (int k = 0; k < 8; k++) {
            if ((k & d) == 0) {
                bool up = (lane & d) != 0;
                float send = up ? a[k] : a[k + d];
                float got  = __shfl_xor_sync(0xffffffffu, send, d);
                if (up) a[k] = got; else a[k + d] = got;
            }
        }
    }
}

// 8 lanes per 8x8 block; lane r owns row r. All DCT coefficients are FFMA
// immediates. low = C^T((C X C^T).*M)C ; high = X - low. x read exactly once.
__global__ __launch_bounds__(256) void dct_main(const float* __restrict__ x,
                                                float* __restrict__ lo,
                                                float* __restrict__ hi)
{
    __shared__ float Ms[64];
    int tid = threadIdx.x;
    if (tid < 64) Ms[tid] = g_M[tid];
    __syncthreads();

    int lane = tid & 7;                       // row (then column) index
    int g    = blockIdx.x * 32 + (tid >> 3);  // global 8x8-block id
    int img  = g >> 6;
    int blk  = g & 63;
    int off  = (img << 12) + ((blk >> 3) << 9) + ((blk & 7) << 3) + (lane << 6);

    const float* xp = x + off;
    float4 a0 = *reinterpret_cast<const float4*>(xp);
    float4 a1 = *reinterpret_cast<const float4*>(xp + 4);
    float X[8] = {a0.x, a0.y, a0.z, a0.w, a1.x, a1.y, a1.z, a1.w};

    // A = Xrow * C^T : A[m] = row_m(C) . Xrow
    float A[8];
    MUL_ROWS(A, X);

    transpose8(A, lane);   // lane now holds column `lane` of A

    // Y = C * A_col, masked with column `lane` of M
    float Y[8];
    MUL_ROWS(Y, A);
    #pragma unroll
    for (int i = 0; i < 8; i++) Y[i] *= Ms[i * 8 + lane];

    // Z = C^T * Y_col
    float Z[8];
    MUL_COLS(Z, Y);

    transpose8(Z, lane);   // lane now holds row `lane` of Z

    // low row = Zrow * C : l[m] = col_m(C) . Zrow
    float l[8];
    MUL_COLS(l, Z);

    float* lp = lo + off;
    float* hp = hi + off;
    *reinterpret_cast<float4*>(lp)     = make_float4(l[0], l[1], l[2], l[3]);
    *reinterpret_cast<float4*>(lp + 4) = make_float4(l[4], l[5], l[6], l[7]);
    *reinterpret_cast<float4*>(hp) =
        make_float4(X[0] - l[0], X[1] - l[1], X[2] - l[2], X[3] - l[3]);
    *reinterpret_cast<float4*>(hp + 4) =
        make_float4(X[4] - l[4], X[5] - l[5], X[6] - l[6], X[7] - l[7]);
}

extern "C" void kernel_launch(void* const* d_in, const int* in_sizes, int n_in,
                              void* d_out, int out_size)
{
    const float* x     = (const float*)d_in[0];
    const float* noise = (const float*)d_in[1];
    const float* qmat  = (const float*)d_in[2];
    const float* qmw   = (const float*)d_in[3];
    const float* w1    = (const float*)d_in[4];
    const float* b1    = (const float*)d_in[5];
    const float* w2    = (const float*)d_in[6];
    const float* b2    = (const float*)d_in[7];
    const float* w3    = (const float*)d_in[8];
    const float* b3    = (const float*)d_in[9];

    float* out = (float*)d_out;
    int N = out_size / 2;                 // elements per output tensor
    float* lo = out;
    float* hi = out + N;

    prep_kernel<<<1, 64>>>(noise, qmat, qmw, w1, b1, w2, b2, w3, b3);

    int nblocks8x8 = N / 64;              // 8 lanes per block, 32 blocks per CTA
    dct_main<<<nblocks8x8 / 32, 256>>>(x, lo, hi);
}

// round 6
// speedup vs baseline: 1.8840x; 1.3836x over previous
#include <cuda_runtime.h>
#include <math.h>

// ---- DCT basis as compile-time immediates (truncated-pi basis, <4e-7 err) --
#define P0 0.35355339059327373f
#define P1 0.4903926402016152f
#define P2 0.46193976625564337f
#define P3 0.4157348061512726f
#define P4 0.3535533905932738f
#define P5 0.2777851165098011f
#define P6 0.1913417161825449f
#define P7 0.09754516100806412f

#define DOT8(v,c0,c1,c2,c3,c4,c5,c6,c7) \
    fmaf((v)[7],(c7),fmaf((v)[6],(c6),fmaf((v)[5],(c5),fmaf((v)[4],(c4), \
    fmaf((v)[3],(c3),fmaf((v)[2],(c2),fmaf((v)[1],(c1),(v)[0]*(c0))))))))

// dst[i] = row_i(C) . src
#define MUL_ROWS(dst, src) do { \
    (dst)[0] = DOT8(src, P0, P0, P0, P0, P0, P0, P0, P0); \
    (dst)[1] = DOT8(src, P1, P3, P5, P7,-P7,-P5,-P3,-P1); \
    (dst)[2] = DOT8(src, P2, P6,-P6,-P2,-P2,-P6, P6, P2); \
    (dst)[3] = DOT8(src, P3,-P7,-P1,-P5, P5, P1, P7,-P3); \
    (dst)[4] = DOT8(src, P4,-P4,-P4, P4, P4,-P4,-P4, P4); \
    (dst)[5] = DOT8(src, P5,-P1, P7, P3,-P3,-P7, P1,-P5); \
    (dst)[6] = DOT8(src, P6,-P2, P2,-P6,-P6, P2,-P2, P6); \
    (dst)[7] = DOT8(src, P7,-P5, P3,-P1, P1,-P3, P5,-P7); \
} while (0)

// dst[i] = col_i(C) . src
#define MUL_COLS(dst, src) do { \
    (dst)[0] = DOT8(src, P0, P1, P2, P3, P4, P5, P6, P7); \
    (dst)[1] = DOT8(src, P0, P3, P6,-P7,-P4,-P1,-P2,-P5); \
    (dst)[2] = DOT8(src, P0, P5,-P6,-P1,-P4, P7, P2, P3); \
    (dst)[3] = DOT8(src, P0, P7,-P2,-P5, P4, P3,-P6,-P1); \
    (dst)[4] = DOT8(src, P0,-P7,-P2, P5, P4,-P3,-P6, P1); \
    (dst)[5] = DOT8(src, P0,-P5,-P6, P1,-P4,-P7, P2,-P3); \
    (dst)[6] = DOT8(src, P0,-P3, P6, P7,-P4, P1,-P2, P5); \
    (dst)[7] = DOT8(src, P0,-P1, P2,-P3, P4,-P5, P6,-P7); \
} while (0)

// learned mask, COLUMN-major: g_Mc[c*8 + i] = M[i][c]
static __device__ float g_Mc[64];

__global__ void prep_kernel(const float* __restrict__ noise,
                            const float* __restrict__ qmat,
                            const float* __restrict__ qmw,
                            const float* __restrict__ w1, const float* __restrict__ b1,
                            const float* __restrict__ w2, const float* __restrict__ b2,
                            const float* __restrict__ w3, const float* __restrict__ b3)
{
    __shared__ float h1[16], h2[16], nr[18], coef[16];
    int t = threadIdx.x;  // 64 threads

    const float inv_sqrt2 = 0.7071067811865476f;
    if (t < 16) {
        float z = fmaf(noise[0], w1[t], b1[t]);
        h1[t] = 0.5f * z * (1.0f + erff(z * inv_sqrt2));
    }
    __syncthreads();
    if (t < 16) {
        float z = b2[t];
        #pragma unroll
        for (int k = 0; k < 16; k++) z = fmaf(h1[k], w2[k * 16 + t], z);
        h2[t] = 0.5f * z * (1.0f + erff(z * inv_sqrt2));
    }
    __syncthreads();
    if (t < 18) {
        float z = b3[t];
        #pragma unroll
        for (int k = 0; k < 16; k++) z = fmaf(h2[k], w3[k * 18 + t], z);
        nr[t] = z;
    }
    __syncthreads();
    if (t == 0) {
        float mx = qmw[0];
        #pragma unroll
        for (int i = 1; i < 16; i++) mx = fmaxf(mx, qmw[i]);
        float e[16], sum = 0.f;
        #pragma unroll
        for (int i = 0; i < 16; i++) { e[i] = expf(qmw[i] - mx); sum += e[i]; }
        float inv = 1.0f / sum;
        #pragma unroll
        for (int i = 0; i < 16; i++)
            coef[i] = (e[i] * inv * nr[0] + nr[1]) * nr[2 + i];
    }
    __syncthreads();

    if (t < 64) {
        int c = t >> 3, i = t & 7;          // write col-major
        float s = 0.f;
        #pragma unroll
        for (int q = 0; q < 16; q++) s = fmaf(coef[q], qmat[q * 64 + i * 8 + c], s);
        g_Mc[t] = s;
    }
}

// 2 lanes per 8x8 block. Lane parity p owns rows [4p,4p+4).
// Transpose = one xor-1 quadrant swap (16 SHFL) + compile-time renames.
// low = C^T((C X C^T).*M)C ; high = X - low. x read exactly once.
__global__ __launch_bounds__(256) void dct_main(const float* __restrict__ x,
                                                float* __restrict__ lo,
                                                float* __restrict__ hi)
{
    __shared__ float Ms[64];               // col-major M
    int tid = threadIdx.x;
    if (tid < 64) Ms[tid] = g_Mc[tid];
    __syncthreads();

    int p   = tid & 1;                     // half-block owner
    int g   = blockIdx.x * 128 + (tid >> 1);   // global 8x8-block id
    int img = g >> 6;
    int blk = g & 63;
    int base = (img << 12) + ((blk >> 3) << 9) + ((blk & 7) << 3);
    int r0   = p << 2;                     // first owned row

    const float* xp = x + base + (r0 << 6);
    float X[32];
    #pragma unroll
    for (int i = 0; i < 4; i++) {
        float4 a = *reinterpret_cast<const float4*>(xp + (i << 6));
        float4 b = *reinterpret_cast<const float4*>(xp + (i << 6) + 4);
        X[i*8+0]=a.x; X[i*8+1]=a.y; X[i*8+2]=a.z; X[i*8+3]=a.w;
        X[i*8+4]=b.x; X[i*8+5]=b.y; X[i*8+6]=b.z; X[i*8+7]=b.w;
    }

    // S1: A rows = (X * C^T) rows 4p+i
    float A[32];
    #pragma unroll
    for (int i = 0; i < 4; i++) MUL_ROWS(&A[i*8], &X[i*8]);

    // T1: quadrant swap with peer lane (xor 1). After this,
    // column c=4p+j of C-X-Ct input is: v[i]=A[i*8+j], v[4+i]=A[i*8+4+j].
    #pragma unroll
    for (int i = 0; i < 4; i++)
        #pragma unroll
        for (int j = 0; j < 4; j++) {
            float send = p ? A[i*8+j] : A[i*8+4+j];
            float got  = __shfl_xor_sync(0xffffffffu, send, 1);
            if (p) A[i*8+j] = got; else A[i*8+4+j] = got;
        }

    // S2+mask+S3 per owned column c = 4p+j (in place in A)
    #pragma unroll
    for (int j = 0; j < 4; j++) {
        float v[8], w[8], z[8];
        #pragma unroll
        for (int i = 0; i < 4; i++) { v[i] = A[i*8+j]; v[4+i] = A[i*8+4+j]; }
        MUL_ROWS(w, v);                    // B col = C * v
        const float4 m0 = *reinterpret_cast<const float4*>(&Ms[(r0+j) << 3]);
        const float4 m1 = *reinterpret_cast<const float4*>(&Ms[((r0+j) << 3) + 4]);
        w[0]*=m0.x; w[1]*=m0.y; w[2]*=m0.z; w[3]*=m0.w;
        w[4]*=m1.x; w[5]*=m1.y; w[6]*=m1.z; w[7]*=m1.w;
        MUL_COLS(z, w);                    // Z col = C^T * (masked)
        #pragma unroll
        for (int i = 0; i < 4; i++) { A[i*8+j] = z[i]; A[i*8+4+j] = z[4+i]; }
    }

    // T2: identical quadrant swap; afterwards A[i*8+m] = Z row (4p+i), col m.
    #pragma unroll
    for (int i = 0; i < 4; i++)
        #pragma unroll
        for (int j = 0; j < 4; j++) {
            float send = p ? A[i*8+j] : A[i*8+4+j];
            float got  = __shfl_xor_sync(0xffffffffu, send, 1);
            if (p) A[i*8+j] = got; else A[i*8+4+j] = got;
        }

    // S4: low rows = Z*C ; high = X - low
    float* lp = lo + base + (r0 << 6);
    float* hp = hi + base + (r0 << 6);
    #pragma unroll
    for (int i = 0; i < 4; i++) {
        float l[8];
        MUL_COLS(l, &A[i*8]);
        *reinterpret_cast<float4*>(lp + (i << 6))     = make_float4(l[0], l[1], l[2], l[3]);
        *reinterpret_cast<float4*>(lp + (i << 6) + 4) = make_float4(l[4], l[5], l[6], l[7]);
        *reinterpret_cast<float4*>(hp + (i << 6)) =
            make_float4(X[i*8+0]-l[0], X[i*8+1]-l[1], X[i*8+2]-l[2], X[i*8+3]-l[3]);
        *reinterpret_cast<float4*>(hp + (i << 6) + 4) =
            make_float4(X[i*8+4]-l[4], X[i*8+5]-l[5], X[i*8+6]-l[6], X[i*8+7]-l[7]);
    }
}

extern "C" void kernel_launch(void* const* d_in, const int* in_sizes, int n_in,
                              void* d_out, int out_size)
{
    const float* x     = (const float*)d_in[0];
    const float* noise = (const float*)d_in[1];
    const float* qmat  = (const float*)d_in[2];
    const float* qmw   = (const float*)d_in[3];
    const float* w1    = (const float*)d_in[4];
    const float* b1    = (const float*)d_in[5];
    const float* w2    = (const float*)d_in[6];
    const float* b2    = (const float*)d_in[7];
    const float* w3    = (const float*)d_in[8];
    const float* b3    = (const float*)d_in[9];

    float* out = (float*)d_out;
    int N = out_size / 2;                 // elements per output tensor
    float* lo = out;
    float* hi = out + N;

    prep_kernel<<<1, 64>>>(noise, qmat, qmw, w1, b1, w2, b2, w3, b3);

    int nblocks8x8 = N / 64;              // 2 lanes per block -> 128 blocks/CTA
    dct_main<<<nblocks8x8 / 128, 256>>>(x, lo, hi);
}